// round 1
// baseline (speedup 1.0000x reference)
#include <cuda_runtime.h>
#include <cuda_bf16.h>

// Problem constants
#define BSZ   512
#define NNODE 22
#define INDIM 128
#define HID   256
#define MROWS (BSZ * NNODE)   // 11264

// Scratch (device globals: no allocation allowed)
__device__ float g_We1c[INDIM * HID];          // folded first-layer weight
__device__ float g_h   [MROWS * HID];          // relu(x @ We1c + be1)
__device__ float g_hs  [BSZ * HID];            // segment sum over 22 nodes
__device__ float g_S   [BSZ * HID];            // hs @ We2 + 22*be2
__device__ float g_t   [BSZ * HID];            // relu(S @ Wn1 + bn1)

// ---------------------------------------------------------------------------
// K0: We1c[k][c] = We1[k][c] + We1[k+128][c]
// ---------------------------------------------------------------------------
__global__ void prep_we1(const float* __restrict__ We1) {
    int i = blockIdx.x * blockDim.x + threadIdx.x;
    if (i < INDIM * HID)
        g_We1c[i] = We1[i] + We1[INDIM * HID + i];
}

// ---------------------------------------------------------------------------
// Generic tiled SGEMM: C = act(A[MxK] @ B[KxN] + biasScale * bias)
// BCAST: write each output row to 22 consecutive output rows (node broadcast)
// ---------------------------------------------------------------------------
template <int BM, int BN, int BK, int TM, int TN, bool RELU, bool BCAST>
__global__ void gemm_bias(int M, int N, int K,
                          const float* __restrict__ A,
                          const float* __restrict__ B,
                          const float* __restrict__ bias,
                          float biasScale,
                          float* __restrict__ C) {
    constexpr int THREADS = (BM * BN) / (TM * TN);

    __shared__ float As[BK][BM + 1];   // +1 pad: avoid 16-way store conflicts
    __shared__ float Bs[BK][BN];

    const int cRow = blockIdx.y;       // M tile
    const int cCol = blockIdx.x;       // N tile
    const int tid  = threadIdx.x;

    const int tCol = tid % (BN / TN);
    const int tRow = tid / (BN / TN);

    // A-tile loader: thread reads column aInnerCol of k-slab, rows strided
    const int aInnerCol = tid % BK;
    const int aInnerRow = tid / BK;
    constexpr int aStride = THREADS / BK;
    // B-tile loader
    const int bInnerCol = tid % BN;
    const int bInnerRow = tid / BN;
    constexpr int bStride = THREADS / BN;

    const float* Ab = A + (size_t)cRow * BM * K;
    const float* Bb = B + (size_t)cCol * BN;

    float acc[TM][TN];
#pragma unroll
    for (int i = 0; i < TM; i++)
#pragma unroll
        for (int j = 0; j < TN; j++) acc[i][j] = 0.0f;

    float regM[TM], regN[TN];

    for (int k0 = 0; k0 < K; k0 += BK) {
#pragma unroll
        for (int r = aInnerRow; r < BM; r += aStride)
            As[aInnerCol][r] = Ab[(size_t)r * K + k0 + aInnerCol];
#pragma unroll
        for (int r = bInnerRow; r < BK; r += bStride)
            Bs[r][bInnerCol] = Bb[(size_t)(k0 + r) * N + bInnerCol];
        __syncthreads();

#pragma unroll
        for (int kk = 0; kk < BK; kk++) {
#pragma unroll
            for (int i = 0; i < TM; i++) regM[i] = As[kk][tRow * TM + i];
#pragma unroll
            for (int j = 0; j < TN; j++) regN[j] = Bs[kk][tCol * TN + j];
#pragma unroll
            for (int i = 0; i < TM; i++)
#pragma unroll
                for (int j = 0; j < TN; j++)
                    acc[i][j] = fmaf(regM[i], regN[j], acc[i][j]);
        }
        __syncthreads();
    }

    // Epilogue
#pragma unroll
    for (int i = 0; i < TM; i++) {
        const int row = cRow * BM + tRow * TM + i;
#pragma unroll
        for (int j = 0; j < TN; j++) {
            const int col = cCol * BN + tCol * TN + j;
            float v = acc[i][j] + biasScale * bias[col];
            if (RELU) v = fmaxf(v, 0.0f);
            if (!BCAST) {
                C[(size_t)row * N + col] = v;
            } else {
#pragma unroll
                for (int p = 0; p < NNODE; p++)
                    C[((size_t)row * NNODE + p) * N + col] = v;
            }
        }
    }
}

// ---------------------------------------------------------------------------
// K2: hs[b][c] = sum_{a<22} h[b*22+a][c]
// ---------------------------------------------------------------------------
__global__ void reduce_nodes() {
    const int b = blockIdx.x;
    const int c = threadIdx.x;           // 256 threads = HID
    const float* base = g_h + (size_t)b * NNODE * HID + c;
    float s = 0.0f;
#pragma unroll
    for (int a = 0; a < NNODE; a++) s += base[(size_t)a * HID];
    g_hs[b * HID + c] = s;
}

// ---------------------------------------------------------------------------
extern "C" void kernel_launch(void* const* d_in, const int* in_sizes, int n_in,
                              void* d_out, int out_size) {
    const float* x   = (const float*)d_in[0];
    const float* We1 = (const float*)d_in[1];
    const float* be1 = (const float*)d_in[2];
    const float* We2 = (const float*)d_in[3];
    const float* be2 = (const float*)d_in[4];
    const float* Wn1 = (const float*)d_in[5];
    const float* bn1 = (const float*)d_in[6];
    const float* Wn2 = (const float*)d_in[7];
    const float* bn2 = (const float*)d_in[8];
    float* out = (float*)d_out;

    float *pWe1c, *ph, *phs, *pS, *pt;
    cudaGetSymbolAddress((void**)&pWe1c, g_We1c);
    cudaGetSymbolAddress((void**)&ph,    g_h);
    cudaGetSymbolAddress((void**)&phs,   g_hs);
    cudaGetSymbolAddress((void**)&pS,    g_S);
    cudaGetSymbolAddress((void**)&pt,    g_t);

    // K0: fold We1 halves
    prep_we1<<<(INDIM * HID + 255) / 256, 256>>>(We1);

    // K1: h = relu(x @ We1c + be1)   [11264 x 256], K=128
    {
        dim3 grid(HID / 64, MROWS / 64);
        gemm_bias<64, 64, 16, 4, 4, true, false><<<grid, 256>>>(
            MROWS, HID, INDIM, x, pWe1c, be1, 1.0f, ph);
    }

    // K2: segment sum over 22 nodes -> hs [512 x 256]
    reduce_nodes<<<BSZ, HID>>>();

    // K3: S = hs @ We2 + 22*be2      [512 x 256], K=256
    {
        dim3 grid(HID / 32, BSZ / 32);
        gemm_bias<32, 32, 16, 2, 2, false, false><<<grid, 256>>>(
            BSZ, HID, HID, phs, We2, be2, (float)NNODE, pS);
    }

    // K4: t = relu(S @ Wn1 + bn1)
    {
        dim3 grid(HID / 32, BSZ / 32);
        gemm_bias<32, 32, 16, 2, 2, true, false><<<grid, 256>>>(
            BSZ, HID, HID, pS, Wn1, bn1, 1.0f, pt);
    }

    // K5: out[b, i, :] = t @ Wn2 + bn2, broadcast over i (22 nodes)
    {
        dim3 grid(HID / 32, BSZ / 32);
        gemm_bias<32, 32, 16, 2, 2, false, true><<<grid, 256>>>(
            BSZ, HID, HID, pt, Wn2, bn2, 1.0f, out);
    }
}

// round 2
// speedup vs baseline: 1.0828x; 1.0828x over previous
#include <cuda_runtime.h>
#include <cuda_bf16.h>

// Problem constants
#define BSZ   512
#define NNODE 22
#define INDIM 128
#define HID   256
#define MROWS (BSZ * NNODE)   // 11264

// Scratch (device globals: no allocation allowed)
__device__ float g_We1c[INDIM * HID];        // folded first-layer weight
__device__ float g_hs  [BSZ * HID];          // segment sum over 22 nodes
__device__ float g_Wt  [3 * HID * HID];      // transposed We2, Wn1, Wn2: Wt[c*256+k]

// ---------------------------------------------------------------------------
// K0a: We1c[k][c] = We1[k][c] + We1[k+128][c]
// ---------------------------------------------------------------------------
__global__ void prep_we1(const float* __restrict__ We1) {
    int i = blockIdx.x * blockDim.x + threadIdx.x;
    if (i < INDIM * HID)
        g_We1c[i] = We1[i] + We1[INDIM * HID + i];
}

// ---------------------------------------------------------------------------
// K0b: tiled transpose of one 256x256 matrix into g_Wt + ofs
// grid (8,8), block (32,8)
// ---------------------------------------------------------------------------
__global__ void transpose_w(const float* __restrict__ W, int ofs) {
    __shared__ float t[32][33];
    int x0 = blockIdx.x * 32, y0 = blockIdx.y * 32;
    int tx = threadIdx.x, ty0 = threadIdx.y;
#pragma unroll
    for (int s = 0; s < 4; s++) {
        int ty = ty0 + s * 8;
        t[ty][tx] = W[(size_t)(y0 + ty) * HID + x0 + tx];
    }
    __syncthreads();
#pragma unroll
    for (int s = 0; s < 4; s++) {
        int ty = ty0 + s * 8;
        g_Wt[ofs + (size_t)(x0 + ty) * HID + y0 + tx] = t[tx][ty];
    }
}

// ---------------------------------------------------------------------------
// K1: fused GEMM1 + 22-node segment reduce.
//   h[m] = relu(x[m] @ We1c + be1);  hs[b] = sum_{a<22} h[b*22+a]
// BM=88 rows = exactly 4 groups of 22.  TM=11 -> each thread's rows lie in
// exactly one group (tRow 0,1 -> g0; 2,3 -> g1; ...).
// grid (4, 128), block 128.
// ---------------------------------------------------------------------------
__global__ __launch_bounds__(128)
void gemm1_fused(const float* __restrict__ x, const float* __restrict__ be1) {
    constexpr int BM = 88, BN = 64, BK = 16, TM = 11, TN = 4;

    __shared__ float As[BK][BM + 1];
    __shared__ float Bs[BK][BN];
    __shared__ float red[4][16][TN];

    const int tid  = threadIdx.x;
    const int tCol = tid & 15;        // 16 col-threads
    const int tRow = tid >> 4;        // 8 row-threads
    const int cCol = blockIdx.x;      // N tile (4)
    const int cRow = blockIdx.y;      // M tile (128)

    const float* Ab = x + (size_t)cRow * BM * INDIM;
    const float* Bb = g_We1c + cCol * BN;

    const int aCol  = tid & 15;       // k within slab
    const int aRow0 = tid >> 4;       // row start, stride 8
    const int bCol  = tid & 63;
    const int bRow0 = tid >> 6;       // stride 2

    float acc[TM][TN];
#pragma unroll
    for (int i = 0; i < TM; i++)
#pragma unroll
        for (int j = 0; j < TN; j++) acc[i][j] = 0.0f;

    for (int k0 = 0; k0 < INDIM; k0 += BK) {
#pragma unroll
        for (int t = 0; t < 11; t++) {
            int r = aRow0 + 8 * t;
            As[aCol][r] = Ab[(size_t)r * INDIM + k0 + aCol];
        }
#pragma unroll
        for (int t = 0; t < 8; t++) {
            int r = bRow0 + 2 * t;
            Bs[r][bCol] = Bb[(size_t)(k0 + r) * HID + bCol];
        }
        __syncthreads();

#pragma unroll
        for (int kk = 0; kk < BK; kk++) {
            float rM[TM], rN[TN];
#pragma unroll
            for (int i = 0; i < TM; i++) rM[i] = As[kk][tRow * TM + i];
#pragma unroll
            for (int j = 0; j < TN; j++) rN[j] = Bs[kk][tCol * TN + j];
#pragma unroll
            for (int i = 0; i < TM; i++)
#pragma unroll
                for (int j = 0; j < TN; j++)
                    acc[i][j] = fmaf(rM[i], rN[j], acc[i][j]);
        }
        __syncthreads();
    }

    // Epilogue: relu+bias per row, then partial sum of this thread's 11 rows
    float part[TN];
#pragma unroll
    for (int j = 0; j < TN; j++) {
        const float b = be1[cCol * BN + tCol * TN + j];
        float s = 0.0f;
#pragma unroll
        for (int i = 0; i < TM; i++)
            s += fmaxf(acc[i][j] + b, 0.0f);
        part[j] = s;
    }

    const int g = tRow >> 1;
    if (tRow & 1) {
#pragma unroll
        for (int j = 0; j < TN; j++) red[g][tCol][j] = part[j];
    }
    __syncthreads();
    if (!(tRow & 1)) {
#pragma unroll
        for (int j = 0; j < TN; j++) {
            float s = part[j] + red[g][tCol][j];
            g_hs[(size_t)(cRow * 4 + g) * HID + cCol * BN + tCol * TN + j] = s;
        }
    }
}

// ---------------------------------------------------------------------------
// Tail: 3 fused 256->256 layers + 22-way broadcast output.
// One block = 4 batch rows, 256 threads (thread c owns output column c).
// ---------------------------------------------------------------------------
__device__ __forceinline__ void layer_dot(const float* __restrict__ Wt,
                                          const float (*src)[HID],
                                          float v[4]) {
    const float4* w4 = (const float4*)Wt;
    float a0 = 0.f, a1 = 0.f, a2 = 0.f, a3 = 0.f;
#pragma unroll 8
    for (int k = 0; k < HID / 4; k++) {
        float4 w  = w4[k];
        float4 s0 = *(const float4*)&src[0][4 * k];
        float4 s1 = *(const float4*)&src[1][4 * k];
        float4 s2 = *(const float4*)&src[2][4 * k];
        float4 s3 = *(const float4*)&src[3][4 * k];
        a0 = fmaf(w.x, s0.x, a0); a0 = fmaf(w.y, s0.y, a0);
        a0 = fmaf(w.z, s0.z, a0); a0 = fmaf(w.w, s0.w, a0);
        a1 = fmaf(w.x, s1.x, a1); a1 = fmaf(w.y, s1.y, a1);
        a1 = fmaf(w.z, s1.z, a1); a1 = fmaf(w.w, s1.w, a1);
        a2 = fmaf(w.x, s2.x, a2); a2 = fmaf(w.y, s2.y, a2);
        a2 = fmaf(w.z, s2.z, a2); a2 = fmaf(w.w, s2.w, a2);
        a3 = fmaf(w.x, s3.x, a3); a3 = fmaf(w.y, s3.y, a3);
        a3 = fmaf(w.z, s3.z, a3); a3 = fmaf(w.w, s3.w, a3);
    }
    v[0] = a0; v[1] = a1; v[2] = a2; v[3] = a3;
}

__global__ __launch_bounds__(256)
void fused_tail(const float* __restrict__ be2,
                const float* __restrict__ bn1,
                const float* __restrict__ bn2,
                float* __restrict__ out) {
    __shared__ float act[2][4][HID];

    const int c  = threadIdx.x;
    const int b0 = blockIdx.x * 4;

#pragma unroll
    for (int r = 0; r < 4; r++)
        act[0][r][c] = g_hs[(size_t)(b0 + r) * HID + c];
    __syncthreads();

    float v[4];

    // Layer 0: S = hs @ We2 + 22*be2   (no relu)
    layer_dot(g_Wt + (size_t)c * HID, act[0], v);
    {
        const float b = 22.0f * be2[c];
#pragma unroll
        for (int r = 0; r < 4; r++) act[1][r][c] = v[r] + b;
    }
    __syncthreads();

    // Layer 1: t = relu(S @ Wn1 + bn1)
    layer_dot(g_Wt + HID * HID + (size_t)c * HID, act[1], v);
    {
        const float b = bn1[c];
#pragma unroll
        for (int r = 0; r < 4; r++) act[0][r][c] = fmaxf(v[r] + b, 0.0f);
    }
    __syncthreads();

    // Layer 2: out = t @ Wn2 + bn2, broadcast to all 22 nodes
    layer_dot(g_Wt + 2 * HID * HID + (size_t)c * HID, act[0], v);
    {
        const float b = bn2[c];
#pragma unroll
        for (int r = 0; r < 4; r++) {
            const float o = v[r] + b;
            size_t base = ((size_t)(b0 + r) * NNODE) * HID + c;
#pragma unroll
            for (int i = 0; i < NNODE; i++)
                out[base + (size_t)i * HID] = o;
        }
    }
}

// ---------------------------------------------------------------------------
extern "C" void kernel_launch(void* const* d_in, const int* in_sizes, int n_in,
                              void* d_out, int out_size) {
    const float* x   = (const float*)d_in[0];
    const float* We1 = (const float*)d_in[1];
    const float* be1 = (const float*)d_in[2];
    const float* We2 = (const float*)d_in[3];
    const float* be2 = (const float*)d_in[4];
    const float* Wn1 = (const float*)d_in[5];
    const float* bn1 = (const float*)d_in[6];
    const float* Wn2 = (const float*)d_in[7];
    const float* bn2 = (const float*)d_in[8];
    float* out = (float*)d_out;

    // K0: fold We1 halves + transpose the three tail weights
    prep_we1<<<(INDIM * HID + 255) / 256, 256>>>(We1);
    {
        dim3 g(8, 8), b(32, 8);
        transpose_w<<<g, b>>>(We2, 0);
        transpose_w<<<g, b>>>(Wn1, HID * HID);
        transpose_w<<<g, b>>>(Wn2, 2 * HID * HID);
    }

    // K1: fused GEMM1 + segment reduce -> g_hs [512 x 256]
    {
        dim3 grid(HID / 64, MROWS / 88);   // (4, 128)
        gemm1_fused<<<grid, 128>>>(x, be1);
    }

    // Tail: 3 layers + broadcast -> out
    fused_tail<<<BSZ / 4, HID>>>(be2, bn1, bn2, out);
}